// round 8
// baseline (speedup 1.0000x reference)
#include <cuda_runtime.h>

#define N 4096
#define D 512
#define NCLASS 100
#define INTRA_BLOCKS 512
#define INTRA_THREADS 256

__device__ float g_zn[N * D];      // normalized z
__device__ float g_eadv[N];        // exp(cos(z, z_adv)/T)
__device__ int   g_count[NCLASS];
__device__ int   g_offset[NCLASS];
__device__ int   g_members[N];     // row indices grouped by class (stable order)
__device__ float g_partial[INTRA_BLOCKS];
__device__ unsigned int g_done;

__constant__ float c_invT = 2.0f;  // 1 / TEMPERATURE
__constant__ float c_eps  = 1e-8f;

// ---------------------------------------------------------------------------
// Fused: blocks [0, N) normalize one row each; block N (extra block) does the
// label decode + STABLE match_any counting sort concurrently on its own SM.
// The sort is independent of the norm output; k_intra (next launch) sees both.
// ---------------------------------------------------------------------------
__global__ void k_norm_labels(const float* __restrict__ z,
                              const float* __restrict__ za,
                              const int* __restrict__ lab) {
    if (blockIdx.x < N) {
        // ---- normalize path ----
        int row = blockIdx.x;
        int t = threadIdx.x;  // 0..127
        const float4* zr  = reinterpret_cast<const float4*>(z  + (size_t)row * D);
        const float4* zar = reinterpret_cast<const float4*>(za + (size_t)row * D);
        float4 v = zr[t];
        float4 w = zar[t];
        float sz = v.x * v.x + v.y * v.y + v.z * v.z + v.w * v.w;
        float sa = w.x * w.x + w.y * w.y + w.z * w.z + w.w * w.w;
        float dd = v.x * w.x + v.y * w.y + v.z * w.z + v.w * w.w;
#pragma unroll
        for (int o = 16; o; o >>= 1) {
            sz += __shfl_xor_sync(0xffffffffu, sz, o);
            sa += __shfl_xor_sync(0xffffffffu, sa, o);
            dd += __shfl_xor_sync(0xffffffffu, dd, o);
        }
        __shared__ float s1[4], s2[4], s3[4];
        int wid = t >> 5, lid = t & 31;
        if (lid == 0) { s1[wid] = sz; s2[wid] = sa; s3[wid] = dd; }
        __syncthreads();
        sz = s1[0] + s1[1] + s1[2] + s1[3];
        sa = s2[0] + s2[1] + s2[2] + s2[3];
        dd = s3[0] + s3[1] + s3[2] + s3[3];

        float invz  = 1.0f / fmaxf(sqrtf(sz), c_eps);
        float invza = 1.0f / fmaxf(sqrtf(sa), c_eps);

        float4 o4 = make_float4(v.x * invz, v.y * invz, v.z * invz, v.w * invz);
        reinterpret_cast<float4*>(g_zn + (size_t)row * D)[t] = o4;

        if (t == 0) g_eadv[row] = expf(dd * invz * invza * c_invT);
        return;
    }

    // ---- label sort path (one block, 128 threads = 4 warps) ----
    __shared__ int sl[N];              // 16 KB decoded labels
    __shared__ int whist[4][NCLASS];   // per-warp class counts/bases
    __shared__ int cls_cnt[NCLASS];
    __shared__ int cls_off[NCLASS];
    __shared__ int ok;
    int t = threadIdx.x;
    int lane = t & 31, w = t >> 5;

    if (t == 0) { ok = 1; g_done = 0u; }
    __syncthreads();
    // int64 labels in [0,100): odd 32-bit words are 0, even in range.
    bool good = true;
    for (int k = t; k < N / 2; k += 128) {
        int lo = lab[2 * k];
        int hi = lab[2 * k + 1];
        if (hi != 0 || lo < 0 || lo >= NCLASS) good = false;
    }
    if (!good) atomicExch(&ok, 0);
    __syncthreads();
    int is64 = ok;

    for (int i = t; i < N; i += 128) sl[i] = is64 ? lab[2 * i] : lab[i];
    for (int c = lane; c < NCLASS; c += 32) whist[w][c] = 0;
    __syncthreads();

    // count pass: warp w owns rows [w*1024, w*1024+1024), 32 iters of 32
    int rbase = w * 1024;
#pragma unroll 1
    for (int it = 0; it < 32; it++) {
        int c = sl[rbase + it * 32 + lane];
        unsigned mask = __match_any_sync(0xffffffffu, c);
        int leader = __ffs(mask) - 1;
        if (lane == leader) whist[w][c] += __popc(mask);
        __syncwarp();
    }
    __syncthreads();

    // cross-warp exclusive scan per class (thread per class, 4 steps)
    if (t < NCLASS) {
        int run = 0;
#pragma unroll
        for (int k = 0; k < 4; k++) {
            int v = whist[k][t];
            whist[k][t] = run;
            run += v;
        }
        cls_cnt[t] = run;
    }
    __syncthreads();

    // class offsets: warp 0, 4 SHFL scan segments over 100 counts
    if (w == 0) {
        int carry = 0;
#pragma unroll
        for (int seg = 0; seg < 4; seg++) {
            int c = seg * 32 + lane;
            int v = (c < NCLASS) ? cls_cnt[c] : 0;
            int inc = v;
#pragma unroll
            for (int o = 1; o < 32; o <<= 1) {
                int y = __shfl_up_sync(0xffffffffu, inc, o);
                if (lane >= o) inc += y;
            }
            if (c < NCLASS) cls_off[c] = inc - v + carry;
            carry += __shfl_sync(0xffffffffu, inc, 31);
        }
    }
    __syncthreads();

    // stable emit: match_any rank within each 32-row group, leader bumps base
#pragma unroll 1
    for (int it = 0; it < 32; it++) {
        int row = rbase + it * 32 + lane;
        int c = sl[row];
        unsigned mask = __match_any_sync(0xffffffffu, c);
        int rank = __popc(mask & ((1u << lane) - 1u));
        int base = whist[w][c];          // same-class lanes broadcast-read
        g_members[cls_off[c] + base + rank] = row;
        int leader = __ffs(mask) - 1;
        if (lane == leader) whist[w][c] = base + __popc(mask);
        __syncwarp();
    }
    if (t < NCLASS) { g_count[t] = cls_cnt[t]; g_offset[t] = cls_off[t]; }
}

// ---------------------------------------------------------------------------
// Main: warp per member slot s (adjacent warps share a class -> L1 reuse).
// 4-way member unroll: four independent dot/shfl/exp chains per iteration.
// Block partial -> g_partial; ticket last-block does the deterministic
// fixed-tree final reduction into out[0].
// ---------------------------------------------------------------------------
__global__ void k_intra(float* __restrict__ out) {
    __shared__ float warp_loss[INTRA_THREADS / 32];
    __shared__ bool is_last;
    int s = (blockIdx.x * blockDim.x + threadIdx.x) >> 5;
    int lane = threadIdx.x & 31;
    int wid = threadIdx.x >> 5;

    int i = g_members[s];
    // class of slot s: binary-search-free — recover from offsets via g_members
    // ordering: find c such that offset[c] <= s < offset[c]+count[c].
    // Cheaper: i's label not stored anymore; derive off/cnt by scanning? Instead
    // store per-slot class implicitly: all lanes know s; use g_offset/g_count
    // via the row's class looked up from the sort: we re-find it by a small
    // linear probe over classes is too slow; so keep using the row's own data:
    // NOTE: we kept g_members grouped; the class bounds come from a per-slot
    // search below (7-step branchless binary search over 100 offsets in L1).
    int lo = 0, hi = NCLASS - 1;
#pragma unroll
    for (int step = 0; step < 7; step++) {   // 2^7 = 128 >= 100
        int mid = (lo + hi + 1) >> 1;
        bool ge = (g_offset[mid] <= s);
        lo = ge ? mid : lo;
        hi = ge ? hi : mid - 1;
    }
    int off = g_offset[lo];
    int cnt = g_count[lo];

    const float4* zi = reinterpret_cast<const float4*>(g_zn + (size_t)i * D);
    float4 r0 = zi[lane], r1 = zi[lane + 32], r2 = zi[lane + 64], r3 = zi[lane + 96];

    float acc = 0.0f;
    int m = 0;
    for (; m + 4 <= cnt; m += 4) {
        int j0 = g_members[off + m];
        int j1 = g_members[off + m + 1];
        int j2 = g_members[off + m + 2];
        int j3 = g_members[off + m + 3];
        const float4* a0 = reinterpret_cast<const float4*>(g_zn + (size_t)j0 * D);
        const float4* a1 = reinterpret_cast<const float4*>(g_zn + (size_t)j1 * D);
        const float4* a2 = reinterpret_cast<const float4*>(g_zn + (size_t)j2 * D);
        const float4* a3 = reinterpret_cast<const float4*>(g_zn + (size_t)j3 * D);
        float s0 = 0.0f, s1 = 0.0f, s2 = 0.0f, s3 = 0.0f;
        float4 p0, p1, p2, p3;
#define DOT_STEP(OFS, R)                                                   \
        p0 = a0[lane + OFS]; p1 = a1[lane + OFS];                          \
        p2 = a2[lane + OFS]; p3 = a3[lane + OFS];                          \
        s0 += R.x*p0.x + R.y*p0.y + R.z*p0.z + R.w*p0.w;                   \
        s1 += R.x*p1.x + R.y*p1.y + R.z*p1.z + R.w*p1.w;                   \
        s2 += R.x*p2.x + R.y*p2.y + R.z*p2.z + R.w*p2.w;                   \
        s3 += R.x*p3.x + R.y*p3.y + R.z*p3.z + R.w*p3.w;
        DOT_STEP(0,  r0)
        DOT_STEP(32, r1)
        DOT_STEP(64, r2)
        DOT_STEP(96, r3)
#undef DOT_STEP
#pragma unroll
        for (int o = 16; o; o >>= 1) {
            s0 += __shfl_xor_sync(0xffffffffu, s0, o);
            s1 += __shfl_xor_sync(0xffffffffu, s1, o);
            s2 += __shfl_xor_sync(0xffffffffu, s2, o);
            s3 += __shfl_xor_sync(0xffffffffu, s3, o);
        }
        float e0 = __expf(s0 * c_invT);
        float e1 = __expf(s1 * c_invT);
        float e2 = __expf(s2 * c_invT);
        float e3 = __expf(s3 * c_invT);
        acc += (j0 != i) ? e0 : 0.0f;
        acc += (j1 != i) ? e1 : 0.0f;
        acc += (j2 != i) ? e2 : 0.0f;
        acc += (j3 != i) ? e3 : 0.0f;
    }
    for (; m < cnt; m++) {
        int j0 = g_members[off + m];
        const float4* a = reinterpret_cast<const float4*>(g_zn + (size_t)j0 * D);
        float s0 = 0.0f;
        float4 p;
        p = a[lane];       s0 += r0.x*p.x + r0.y*p.y + r0.z*p.z + r0.w*p.w;
        p = a[lane + 32];  s0 += r1.x*p.x + r1.y*p.y + r1.z*p.z + r1.w*p.w;
        p = a[lane + 64];  s0 += r2.x*p.x + r2.y*p.y + r2.z*p.z + r2.w*p.w;
        p = a[lane + 96];  s0 += r3.x*p.x + r3.y*p.y + r3.z*p.z + r3.w*p.w;
#pragma unroll
        for (int o = 16; o; o >>= 1) s0 += __shfl_xor_sync(0xffffffffu, s0, o);
        acc += (j0 != i) ? __expf(s0 * c_invT) : 0.0f;
    }

    // per-warp loss -> block partial (fixed order => deterministic)
    if (lane == 0) warp_loss[wid] = log1pf(acc / g_eadv[i]);
    __syncthreads();
    if (threadIdx.x == 0) {
        float bsum = 0.0f;
#pragma unroll
        for (int ww = 0; ww < INTRA_THREADS / 32; ww++) bsum += warp_loss[ww];
        g_partial[blockIdx.x] = bsum;
        __threadfence();
        unsigned int ticket = atomicAdd(&g_done, 1u);
        is_last = (ticket == INTRA_BLOCKS - 1);
    }
    __syncthreads();

    // last-arriving block: deterministic fixed-tree reduction of 512 partials
    if (is_last) {
        __shared__ float sm[INTRA_THREADS];
        int t = threadIdx.x;
        __threadfence();
        sm[t] = g_partial[t] + g_partial[t + INTRA_THREADS];
        __syncthreads();
#pragma unroll
        for (int o = INTRA_THREADS / 2; o > 0; o >>= 1) {
            if (t < o) sm[t] += sm[t + o];
            __syncthreads();
        }
        if (t == 0) out[0] = sm[0] * (1.0f / (float)N);
    }
}

extern "C" void kernel_launch(void* const* d_in, const int* in_sizes, int n_in,
                              void* d_out, int out_size) {
    const float* z   = (const float*)d_in[0];
    const float* za  = (const float*)d_in[1];
    const int*   lab = (const int*)d_in[2];
    float* out = (float*)d_out;

    k_norm_labels<<<N + 1, 128>>>(z, za, lab);
    k_intra<<<INTRA_BLOCKS, INTRA_THREADS>>>(out);
}